// round 11
// baseline (speedup 1.0000x reference)
#include <cuda_runtime.h>
#include <math.h>

#define NB 128
#define NS 20
#define NT 19
#define NE 512
#define NH 512
#define NV 10000
#define NG 2048               // 4*H
#define PRED (NB*NT*NV)       // 24,320,000 prediction elements

// ---------------- device scratch (no cudaMalloc allowed) ----------------
__device__ int   d_sort_ind[NB];
__device__ int   d_dec_len[NB];
__device__ float d_Xin[NS*NB*NE];       // gathered step inputs   (2560 x 512)
__device__ float d_Xproj[NS*NB*NG];     // x@Wih^T + b            (2560 x 2048)
__device__ float d_hA[NB*NH];
__device__ float d_hB[NB*NH];
__device__ float d_cst[NB*NH];
__device__ float d_Hbuf[NT*NB*NH];      // h_t for t'=0..18       (2432 x 512)

// ---------------- sort + metadata tail ----------------
__global__ __launch_bounds__(NB) void sort_meta_kernel(
        const int* __restrict__ length,
        const int* __restrict__ captions,
        float* __restrict__ out, int write_tail) {
    __shared__ int lens[NB];
    int i = threadIdx.x;
    lens[i] = length[i];
    __syncthreads();
    int li = lens[i];
    int rank = 0;
    #pragma unroll 8
    for (int j = 0; j < NB; j++) {
        int lj = lens[j];
        if (lj > li || (lj == li && j < i)) rank++;
    }
    d_sort_ind[rank] = i;
    d_dec_len[rank] = li - 1;
    __syncthreads();
    if (write_tail) {
        out[PRED + NB*NS + i]      = (float)d_dec_len[i];
        out[PRED + NB*NS + NB + i] = (float)d_sort_ind[i];
        int si = d_sort_ind[i];
        #pragma unroll
        for (int t = 0; t < NS; t++)
            out[PRED + i*NS + t] = (float)captions[si*NS + t];
    }
}

// ---------------- gather step inputs ----------------
__global__ __launch_bounds__(128) void gather_kernel(
        const float* __restrict__ images,
        const int* __restrict__ captions,
        const float* __restrict__ emb) {
    int r = blockIdx.x;
    int s = r >> 7, b = r & (NB - 1);
    int sb = d_sort_ind[b];
    const float4* src;
    if (s == 0) {
        src = (const float4*)(images + (size_t)sb * NE);
    } else {
        int tok = captions[sb * NS + (s - 1)];
        src = (const float4*)(emb + (size_t)tok * NE);
    }
    float4* dst = (float4*)(d_Xin + (size_t)r * NE);
    dst[threadIdx.x] = src[threadIdx.x];
}

// ---------------- shared GEMM core: 128x128x8 tile, double-buffered ----------------
// 256 threads, 8x8 micro-tile. Caller supplies A/B row pointers (k-major, ld=K).
template <int K>
__device__ __forceinline__ void gemm_tile_db(
        const float* Aptr, const float* Bptr, bool bvalid, float acc[8][8]) {
    __shared__ __align__(16) float As[2][8][132];
    __shared__ __align__(16) float Bs[2][8][132];
    int tid = threadIdx.x;
    int arow = tid >> 1, ak4 = (tid & 1) << 2;
    int ty = tid >> 4, tx = tid & 15;

    // prologue: load tile 0
    float4 av = *(const float4*)(Aptr);
    float4 bv = make_float4(0.f, 0.f, 0.f, 0.f);
    if (bvalid) bv = *(const float4*)(Bptr);
    As[0][ak4+0][arow] = av.x; As[0][ak4+1][arow] = av.y;
    As[0][ak4+2][arow] = av.z; As[0][ak4+3][arow] = av.w;
    Bs[0][ak4+0][arow] = bv.x; Bs[0][ak4+1][arow] = bv.y;
    Bs[0][ak4+2][arow] = bv.z; Bs[0][ak4+3][arow] = bv.w;
    __syncthreads();

    int buf = 0;
    for (int kt = 8; kt <= K; kt += 8) {
        float4 nav, nbv;
        bool more = (kt < K);
        if (more) {
            nav = *(const float4*)(Aptr + kt);
            nbv = make_float4(0.f, 0.f, 0.f, 0.f);
            if (bvalid) nbv = *(const float4*)(Bptr + kt);
        }
        #pragma unroll
        for (int kk = 0; kk < 8; kk++) {
            float4 a0 = *(const float4*)&As[buf][kk][ty*8];
            float4 a1 = *(const float4*)&As[buf][kk][ty*8+4];
            float4 b0 = *(const float4*)&Bs[buf][kk][tx*8];
            float4 b1 = *(const float4*)&Bs[buf][kk][tx*8+4];
            float a[8]  = {a0.x,a0.y,a0.z,a0.w,a1.x,a1.y,a1.z,a1.w};
            float bb[8] = {b0.x,b0.y,b0.z,b0.w,b1.x,b1.y,b1.z,b1.w};
            #pragma unroll
            for (int i = 0; i < 8; i++)
                #pragma unroll
                for (int j = 0; j < 8; j++) acc[i][j] += a[i] * bb[j];
        }
        if (more) {
            int nb = buf ^ 1;
            As[nb][ak4+0][arow] = nav.x; As[nb][ak4+1][arow] = nav.y;
            As[nb][ak4+2][arow] = nav.z; As[nb][ak4+3][arow] = nav.w;
            Bs[nb][ak4+0][arow] = nbv.x; Bs[nb][ak4+1][arow] = nbv.y;
            Bs[nb][ak4+2][arow] = nbv.z; Bs[nb][ak4+3][arow] = nbv.w;
            __syncthreads();
            buf = nb;
        }
    }
}

// ---------------- GEMM 1: Xproj = Xin @ Wih^T + (bih + bhh) ----------------
__global__ __launch_bounds__(256) void gemm_xproj_kernel(
        const float* __restrict__ Wih,
        const float* __restrict__ bih,
        const float* __restrict__ bhh) {
    int tid = threadIdx.x;
    int bn = blockIdx.x, bm = blockIdx.y;
    int arow = tid >> 1, ak4 = (tid & 1) << 2;
    const float* Aptr = d_Xin + ((size_t)(bm * 128 + arow)) * NE + ak4;
    const float* Bptr = Wih   + ((size_t)(bn * 128 + arow)) * NE + ak4;
    float acc[8][8];
    #pragma unroll
    for (int i = 0; i < 8; i++)
        #pragma unroll
        for (int j = 0; j < 8; j++) acc[i][j] = 0.f;

    gemm_tile_db<NE>(Aptr, Bptr, true, acc);

    int ty = tid >> 4, tx = tid & 15;
    #pragma unroll
    for (int i = 0; i < 8; i++) {
        int r = bm * 128 + ty * 8 + i;
        float* crow = d_Xproj + (size_t)r * NG;
        #pragma unroll
        for (int j = 0; j < 8; j++) {
            int n = bn * 128 + tx * 8 + j;
            crow[n] = acc[i][j] + bih[n] + bhh[n];
        }
    }
}

// ---------------- fused recurrence step ----------------
__global__ __launch_bounds__(256) void cell_kernel(int s, const float* __restrict__ Whh) {
    const float* hprev = (s & 1) ? d_hB : d_hA;
    float*       hnext = (s & 1) ? d_hA : d_hB;
    int jt = blockIdx.x;      // 0..15
    int mt = blockIdx.y;      // 0..7
    int tid = threadIdx.x;    // 256
    __shared__ float Hs[16][17];
    __shared__ float Ws[128][17];
    __shared__ float Gs[16][129];
    float acc[2][4] = {{0,0,0,0},{0,0,0,0}};
    int m0 = (tid & 7) * 2;
    int c0 = (tid >> 3) * 4;

    if (s > 0) {
        for (int kt = 0; kt < NH; kt += 16) {
            {
                int mm = tid >> 4, k2 = tid & 15;
                Hs[mm][k2] = hprev[(size_t)(mt*16 + mm) * NH + kt + k2];
            }
            #pragma unroll
            for (int u = 0; u < 8; u++) {
                int idx = u * 256 + tid;
                int cc = idx >> 4, k2 = idx & 15;
                int n = (cc >> 5) * NH + jt * 32 + (cc & 31);
                Ws[cc][k2] = Whh[(size_t)n * NH + kt + k2];
            }
            __syncthreads();
            #pragma unroll
            for (int k2 = 0; k2 < 16; k2++) {
                float a0 = Hs[m0][k2], a1 = Hs[m0+1][k2];
                #pragma unroll
                for (int u = 0; u < 4; u++) {
                    float bv = Ws[c0+u][k2];
                    acc[0][u] += a0 * bv;
                    acc[1][u] += a1 * bv;
                }
            }
            __syncthreads();
        }
    }
    #pragma unroll
    for (int u = 0; u < 4; u++) {
        Gs[m0  ][c0+u] = acc[0][u];
        Gs[m0+1][c0+u] = acc[1][u];
    }
    __syncthreads();

    for (int p = tid; p < 512; p += 256) {
        int mm = p >> 5, jj = p & 31;
        int row = mt * 16 + mm;
        int jg  = jt * 32 + jj;
        const float* xp = d_Xproj + ((size_t)(s * NB + row)) * NG;
        float gi = Gs[mm][jj]       + xp[jg];
        float gf = Gs[mm][32 + jj]  + xp[NH + jg];
        float gg = Gs[mm][64 + jj]  + xp[2*NH + jg];
        float go = Gs[mm][96 + jj]  + xp[3*NH + jg];
        float ig = 1.f / (1.f + expf(-gi));
        float fg = 1.f / (1.f + expf(-gf));
        float og = 1.f / (1.f + expf(-go));
        float gt = tanhf(gg);
        float cold = (s == 0) ? 0.f : d_cst[row * NH + jg];
        float cn = fg * cold + ig * gt;
        float hn = og * tanhf(cn);
        d_cst[row * NH + jg] = cn;
        hnext[row * NH + jg] = hn;
        if (s >= 1)
            d_Hbuf[((size_t)(s - 1) * NB + row) * NH + jg] = hn;
    }
}

// ---------------- GEMM 2: preds = Hbuf @ fcw^T + fcb, masked + scattered ----------------
__global__ __launch_bounds__(256) void gemm_fc_kernel(
        const float* __restrict__ fcw,
        const float* __restrict__ fcb,
        float* __restrict__ out) {
    int tid = threadIdx.x;
    int bn = blockIdx.x, bm = blockIdx.y;
    int arow = tid >> 1, ak4 = (tid & 1) << 2;
    const float* Aptr = d_Hbuf + ((size_t)(bm * 128 + arow)) * NH + ak4;
    int brow = bn * 128 + arow;
    bool bvalid = (brow < NV);
    const float* Bptr = fcw + (size_t)(bvalid ? brow : 0) * NH + ak4;
    float acc[8][8];
    #pragma unroll
    for (int i = 0; i < 8; i++)
        #pragma unroll
        for (int j = 0; j < 8; j++) acc[i][j] = 0.f;

    gemm_tile_db<NH>(Aptr, Bptr, bvalid, acc);

    int ty = tid >> 4, tx = tid & 15;
    #pragma unroll
    for (int i = 0; i < 8; i++) {
        int r = bm * 128 + ty * 8 + i;      // r = t'*128 + b
        int tp = r >> 7, bb2 = r & 127;
        int on = (d_dec_len[bb2] > tp);
        float* orow = out + (size_t)bb2 * (NT * NV) + (size_t)tp * NV;
        #pragma unroll
        for (int j = 0; j < 8; j++) {
            int n = bn * 128 + tx * 8 + j;
            if (n < NV) orow[n] = on ? (acc[i][j] + fcb[n]) : 0.f;
        }
    }
}

// ---------------- launch ----------------
extern "C" void kernel_launch(void* const* d_in, const int* in_sizes, int n_in,
                              void* d_out, int out_size) {
    const float* images   = (const float*)d_in[0];
    const int*   captions = (const int*)  d_in[1];
    const int*   length   = (const int*)  d_in[2];
    const float* emb      = (const float*)d_in[3];
    const float* Wih      = (const float*)d_in[4];
    const float* Whh      = (const float*)d_in[5];
    const float* bih      = (const float*)d_in[6];
    const float* bhh      = (const float*)d_in[7];
    const float* fcw      = (const float*)d_in[8];
    const float* fcb      = (const float*)d_in[9];
    float* out = (float*)d_out;

    int write_tail = (out_size >= PRED + NB*NS + 2*NB) ? 1 : 0;

    sort_meta_kernel<<<1, NB>>>(length, captions, out, write_tail);
    gather_kernel<<<NS * NB, 128>>>(images, captions, emb);
    gemm_xproj_kernel<<<dim3(NG / 128, (NS * NB) / 128), 256>>>(Wih, bih, bhh);
    for (int s = 0; s < NS; s++)
        cell_kernel<<<dim3(16, 8), 256>>>(s, Whh);
    gemm_fc_kernel<<<dim3((NV + 127) / 128, (NT * NB) / 128), 256>>>(fcw, fcb, out);
}

// round 16
// speedup vs baseline: 1.5418x; 1.5418x over previous
#include <cuda_runtime.h>
#include <cuda_bf16.h>
#include <math.h>
#include <stdint.h>

#define NB 128
#define NS 20
#define NT 19
#define NE 512
#define NH 512
#define NV 10000
#define NVP 10112             // 79*128 padded vocab
#define NG 2048               // 4*H
#define PRED (NB*NT*NV)       // 24,320,000 prediction elements

// ---------------- device scratch (no cudaMalloc allowed) ----------------
__device__ int   d_sort_ind[NB];
__device__ int   d_dec_len[NB];
__device__ float d_Xin[NS*NB*NE];
__device__ float d_Xproj[NS*NB*NG];
__device__ float d_hA[NB*NH];
__device__ float d_hB[NB*NH];
__device__ float d_cst[NB*NH];
__device__ float d_Hbuf[NT*NB*NH];                 // h_t, rows r = t'*128 + b
__device__ __nv_bfloat16 d_Whi[(size_t)NVP*NH];    // fcw split hi (padded rows zero)
__device__ __nv_bfloat16 d_Wlo[(size_t)NVP*NH];
__device__ __nv_bfloat16 d_Hhi[NT*NB*NH];
__device__ __nv_bfloat16 d_Hlo[NT*NB*NH];

// ---------------- helpers ----------------
__device__ __forceinline__ uint32_t smem_to_u32(const void* p) {
    uint32_t a;
    asm("{ .reg .u64 t; cvta.to.shared.u64 t, %1; cvt.u32.u64 %0, t; }" : "=r"(a) : "l"(p));
    return a;
}
#define SMEM_SWIZZLE_128B(x) ((x) ^ (((x) >> 3) & 0x70))

#define MMA16816(c, a, b0_, b1_) \
    asm volatile("mma.sync.aligned.m16n8k16.row.col.f32.bf16.bf16.f32 " \
        "{%0,%1,%2,%3}, {%4,%5,%6,%7}, {%8,%9}, {%0,%1,%2,%3};" \
        : "+f"((c)[0]), "+f"((c)[1]), "+f"((c)[2]), "+f"((c)[3]) \
        : "r"((a)[0]), "r"((a)[1]), "r"((a)[2]), "r"((a)[3]), "r"(b0_), "r"(b1_))

#define LDMATRIX_X4(r0, r1, r2, r3, ad) \
    asm volatile("ldmatrix.sync.aligned.m8n8.x4.shared.b16 {%0,%1,%2,%3}, [%4];" \
        : "=r"(r0), "=r"(r1), "=r"(r2), "=r"(r3) : "r"(ad))

// ---------------- sort + metadata tail ----------------
__global__ __launch_bounds__(NB) void sort_meta_kernel(
        const int* __restrict__ length, const int* __restrict__ captions,
        float* __restrict__ out, int write_tail) {
    __shared__ int lens[NB];
    int i = threadIdx.x;
    lens[i] = length[i];
    __syncthreads();
    int li = lens[i];
    int rank = 0;
    #pragma unroll 8
    for (int j = 0; j < NB; j++) {
        int lj = lens[j];
        if (lj > li || (lj == li && j < i)) rank++;
    }
    d_sort_ind[rank] = i;
    d_dec_len[rank] = li - 1;
    __syncthreads();
    if (write_tail) {
        out[PRED + NB*NS + i]      = (float)d_dec_len[i];
        out[PRED + NB*NS + NB + i] = (float)d_sort_ind[i];
        int si = d_sort_ind[i];
        #pragma unroll
        for (int t = 0; t < NS; t++)
            out[PRED + i*NS + t] = (float)captions[si*NS + t];
    }
}

// ---------------- gather step inputs ----------------
__global__ __launch_bounds__(128) void gather_kernel(
        const float* __restrict__ images, const int* __restrict__ captions,
        const float* __restrict__ emb) {
    int r = blockIdx.x;
    int s = r >> 7, b = r & (NB - 1);
    int sb = d_sort_ind[b];
    const float4* src;
    if (s == 0) src = (const float4*)(images + (size_t)sb * NE);
    else {
        int tok = captions[sb * NS + (s - 1)];
        src = (const float4*)(emb + (size_t)tok * NE);
    }
    ((float4*)(d_Xin + (size_t)r * NE))[threadIdx.x] = src[threadIdx.x];
}

// ---------------- bf16 hi/lo split converters ----------------
__global__ __launch_bounds__(256) void cvt_w_kernel(const float* __restrict__ fcw) {
    size_t idx = (size_t)blockIdx.x * 256 + threadIdx.x;
    if (idx >= (size_t)NVP * NH) return;
    size_t row = idx / NH;
    float x = (row < NV) ? fcw[idx] : 0.f;
    __nv_bfloat16 hi = __float2bfloat16(x);
    d_Whi[idx] = hi;
    d_Wlo[idx] = __float2bfloat16(x - __bfloat162float(hi));
}
__global__ __launch_bounds__(256) void cvt_h_kernel() {
    size_t idx = (size_t)blockIdx.x * 256 + threadIdx.x;
    if (idx >= (size_t)NT * NB * NH) return;
    float x = d_Hbuf[idx];
    __nv_bfloat16 hi = __float2bfloat16(x);
    d_Hhi[idx] = hi;
    d_Hlo[idx] = __float2bfloat16(x - __bfloat162float(hi));
}

// ---------------- shared GEMM core (SIMT, kept for xproj) ----------------
template <int K>
__device__ __forceinline__ void gemm_tile_db(
        const float* Aptr, const float* Bptr, bool bvalid, float acc[8][8]) {
    __shared__ __align__(16) float As[2][8][132];
    __shared__ __align__(16) float Bs[2][8][132];
    int tid = threadIdx.x;
    int arow = tid >> 1, ak4 = (tid & 1) << 2;
    int ty = tid >> 4, tx = tid & 15;
    float4 av = *(const float4*)(Aptr);
    float4 bv = make_float4(0.f, 0.f, 0.f, 0.f);
    if (bvalid) bv = *(const float4*)(Bptr);
    As[0][ak4+0][arow] = av.x; As[0][ak4+1][arow] = av.y;
    As[0][ak4+2][arow] = av.z; As[0][ak4+3][arow] = av.w;
    Bs[0][ak4+0][arow] = bv.x; Bs[0][ak4+1][arow] = bv.y;
    Bs[0][ak4+2][arow] = bv.z; Bs[0][ak4+3][arow] = bv.w;
    __syncthreads();
    int buf = 0;
    for (int kt = 8; kt <= K; kt += 8) {
        float4 nav, nbv;
        bool more = (kt < K);
        if (more) {
            nav = *(const float4*)(Aptr + kt);
            nbv = make_float4(0.f, 0.f, 0.f, 0.f);
            if (bvalid) nbv = *(const float4*)(Bptr + kt);
        }
        #pragma unroll
        for (int kk = 0; kk < 8; kk++) {
            float4 a0 = *(const float4*)&As[buf][kk][ty*8];
            float4 a1 = *(const float4*)&As[buf][kk][ty*8+4];
            float4 b0 = *(const float4*)&Bs[buf][kk][tx*8];
            float4 b1 = *(const float4*)&Bs[buf][kk][tx*8+4];
            float a[8]  = {a0.x,a0.y,a0.z,a0.w,a1.x,a1.y,a1.z,a1.w};
            float bb[8] = {b0.x,b0.y,b0.z,b0.w,b1.x,b1.y,b1.z,b1.w};
            #pragma unroll
            for (int i = 0; i < 8; i++)
                #pragma unroll
                for (int j = 0; j < 8; j++) acc[i][j] += a[i] * bb[j];
        }
        if (more) {
            int nb = buf ^ 1;
            As[nb][ak4+0][arow] = nav.x; As[nb][ak4+1][arow] = nav.y;
            As[nb][ak4+2][arow] = nav.z; As[nb][ak4+3][arow] = nav.w;
            Bs[nb][ak4+0][arow] = nbv.x; Bs[nb][ak4+1][arow] = nbv.y;
            Bs[nb][ak4+2][arow] = nbv.z; Bs[nb][ak4+3][arow] = nbv.w;
            __syncthreads();
            buf = nb;
        }
    }
}

// ---------------- GEMM 1: Xproj = Xin @ Wih^T + (bih + bhh) ----------------
__global__ __launch_bounds__(256) void gemm_xproj_kernel(
        const float* __restrict__ Wih, const float* __restrict__ bih,
        const float* __restrict__ bhh) {
    int tid = threadIdx.x;
    int bn = blockIdx.x, bm = blockIdx.y;
    int arow = tid >> 1, ak4 = (tid & 1) << 2;
    const float* Aptr = d_Xin + ((size_t)(bm * 128 + arow)) * NE + ak4;
    const float* Bptr = Wih   + ((size_t)(bn * 128 + arow)) * NE + ak4;
    float acc[8][8];
    #pragma unroll
    for (int i = 0; i < 8; i++)
        #pragma unroll
        for (int j = 0; j < 8; j++) acc[i][j] = 0.f;
    gemm_tile_db<NE>(Aptr, Bptr, true, acc);
    int ty = tid >> 4, tx = tid & 15;
    #pragma unroll
    for (int i = 0; i < 8; i++) {
        int r = bm * 128 + ty * 8 + i;
        float* crow = d_Xproj + (size_t)r * NG;
        #pragma unroll
        for (int j = 0; j < 8; j++) {
            int n = bn * 128 + tx * 8 + j;
            crow[n] = acc[i][j] + bih[n] + bhh[n];
        }
    }
}

// ---------------- fused recurrence step ----------------
__global__ __launch_bounds__(256) void cell_kernel(int s, const float* __restrict__ Whh) {
    const float* hprev = (s & 1) ? d_hB : d_hA;
    float*       hnext = (s & 1) ? d_hA : d_hB;
    int jt = blockIdx.x, mt = blockIdx.y, tid = threadIdx.x;
    __shared__ float Hs[16][17];
    __shared__ float Ws[128][17];
    __shared__ float Gs[16][129];
    float acc[2][4] = {{0,0,0,0},{0,0,0,0}};
    int m0 = (tid & 7) * 2;
    int c0 = (tid >> 3) * 4;
    if (s > 0) {
        for (int kt = 0; kt < NH; kt += 16) {
            {
                int mm = tid >> 4, k2 = tid & 15;
                Hs[mm][k2] = hprev[(size_t)(mt*16 + mm) * NH + kt + k2];
            }
            #pragma unroll
            for (int u = 0; u < 8; u++) {
                int idx = u * 256 + tid;
                int cc = idx >> 4, k2 = idx & 15;
                int n = (cc >> 5) * NH + jt * 32 + (cc & 31);
                Ws[cc][k2] = Whh[(size_t)n * NH + kt + k2];
            }
            __syncthreads();
            #pragma unroll
            for (int k2 = 0; k2 < 16; k2++) {
                float a0 = Hs[m0][k2], a1 = Hs[m0+1][k2];
                #pragma unroll
                for (int u = 0; u < 4; u++) {
                    float bv = Ws[c0+u][k2];
                    acc[0][u] += a0 * bv;
                    acc[1][u] += a1 * bv;
                }
            }
            __syncthreads();
        }
    }
    #pragma unroll
    for (int u = 0; u < 4; u++) {
        Gs[m0  ][c0+u] = acc[0][u];
        Gs[m0+1][c0+u] = acc[1][u];
    }
    __syncthreads();
    for (int p = tid; p < 512; p += 256) {
        int mm = p >> 5, jj = p & 31;
        int row = mt * 16 + mm;
        int jg  = jt * 32 + jj;
        const float* xp = d_Xproj + ((size_t)(s * NB + row)) * NG;
        float gi = Gs[mm][jj]       + xp[jg];
        float gf = Gs[mm][32 + jj]  + xp[NH + jg];
        float gg = Gs[mm][64 + jj]  + xp[2*NH + jg];
        float go = Gs[mm][96 + jj]  + xp[3*NH + jg];
        float ig = 1.f / (1.f + expf(-gi));
        float fg = 1.f / (1.f + expf(-gf));
        float og = 1.f / (1.f + expf(-go));
        float gt = tanhf(gg);
        float cold = (s == 0) ? 0.f : d_cst[row * NH + jg];
        float cn = fg * cold + ig * gt;
        float hn = og * tanhf(cn);
        d_cst[row * NH + jg] = cn;
        hnext[row * NH + jg] = hn;
        if (s >= 1)
            d_Hbuf[((size_t)(s - 1) * NB + row) * NH + jg] = hn;
    }
}

// ---------------- GEMM 2: mma.sync bf16-split fc GEMM ----------------
// D[128x128] = H[128x512] x W[128x512]^T via 3-term hi/lo split:
//   Ahi*Bhi + Ahi*Blo + Alo*Bhi  (fp32 accum, mma.m16n8k16)
// 24 chunks (3 terms x 8 k-chunks of 64), cp.async double-buffered.
#define FC_CHUNKS 24
#define FC_SMEM   65536   // 2 bufs x (A 16KB + B 16KB)

__device__ __forceinline__ void fc_issue_chunk(uint32_t sb, int buf, int ch,
                                               int bm, int bn, int tid) {
    int term = ch >> 3, k0 = (ch & 7) * 64;
    const __nv_bfloat16* As = ((term == 2) ? d_Hlo : d_Hhi) + (size_t)(bm * 128) * NH + k0;
    const __nv_bfloat16* Bs = ((term == 1) ? d_Wlo : d_Whi) + (size_t)(bn * 128) * NH + k0;
    uint32_t Ab = sb + buf * 32768, Bb = Ab + 16384;
    #pragma unroll
    for (int t = 0; t < 4; t++) {
        int i = t * 256 + tid;
        int r = i >> 3, s = i & 7;          // row 0..127, 16B segment 0..7
        uint32_t off = SMEM_SWIZZLE_128B((uint32_t)(r * 128 + s * 16));
        const void* ga = As + (size_t)r * NH + s * 8;
        const void* gb = Bs + (size_t)r * NH + s * 8;
        asm volatile("cp.async.cg.shared.global [%0], [%1], 16;" :: "r"(Ab + off), "l"(ga));
        asm volatile("cp.async.cg.shared.global [%0], [%1], 16;" :: "r"(Bb + off), "l"(gb));
    }
    asm volatile("cp.async.commit_group;" ::: "memory");
}

__global__ __launch_bounds__(256, 2) void fc_mma_kernel(
        const float* __restrict__ fcb, float* __restrict__ out) {
    extern __shared__ char smem[];
    uint32_t sb = smem_to_u32(smem);
    int tid = threadIdx.x, lane = tid & 31, w = tid >> 5;
    int bn = blockIdx.x, bm = blockIdx.y;
    int m0 = (w & 3) * 32;       // warp tile: 32 m-rows
    int n0 = (w >> 2) * 64;      // 64 n-cols

    float acc[2][8][4];
    #pragma unroll
    for (int i = 0; i < 2; i++)
        #pragma unroll
        for (int j = 0; j < 8; j++)
            #pragma unroll
            for (int k = 0; k < 4; k++) acc[i][j][k] = 0.f;

    fc_issue_chunk(sb, 0, 0, bm, bn, tid);

    for (int ch = 0; ch < FC_CHUNKS; ch++) {
        if (ch + 1 < FC_CHUNKS) {
            fc_issue_chunk(sb, (ch + 1) & 1, ch + 1, bm, bn, tid);
            asm volatile("cp.async.wait_group 1;" ::: "memory");
        } else {
            asm volatile("cp.async.wait_group 0;" ::: "memory");
        }
        __syncthreads();

        uint32_t Ab = sb + (ch & 1) * 32768, Bb = Ab + 16384;
        #pragma unroll
        for (int kk = 0; kk < 4; kk++) {
            uint32_t a[2][4];
            #pragma unroll
            for (int mf = 0; mf < 2; mf++) {
                int row = m0 + mf * 16 + ((lane >> 3) & 1) * 8 + (lane & 7);
                int col = kk * 16 + (lane >> 4) * 8;
                uint32_t ad = Ab + SMEM_SWIZZLE_128B((uint32_t)(row * 128 + col * 2));
                LDMATRIX_X4(a[mf][0], a[mf][1], a[mf][2], a[mf][3], ad);
            }
            #pragma unroll
            for (int nn = 0; nn < 4; nn++) {
                uint32_t b0, b1, b2, b3;
                int row = n0 + nn * 16 + (lane >> 4) * 8 + (lane & 7);
                int col = kk * 16 + ((lane >> 3) & 1) * 8;
                uint32_t bd = Bb + SMEM_SWIZZLE_128B((uint32_t)(row * 128 + col * 2));
                LDMATRIX_X4(b0, b1, b2, b3, bd);
                #pragma unroll
                for (int mf = 0; mf < 2; mf++) {
                    MMA16816(acc[mf][nn*2+0], a[mf], b0, b1);
                    MMA16816(acc[mf][nn*2+1], a[mf], b2, b3);
                }
            }
        }
        __syncthreads();
    }

    // epilogue: fragment layout D 16x8 -> rows g/g+8, cols tg*2, tg*2+1
    int g = lane >> 2, tg = lane & 3;
    #pragma unroll
    for (int mf = 0; mf < 2; mf++) {
        int rb0 = m0 + mf * 16 + g;      // batch rows rb0, rb0+8
        int on0 = d_dec_len[rb0] > bm;
        int on1 = d_dec_len[rb0 + 8] > bm;
        float* o0 = out + (size_t)rb0 * (NT * NV) + (size_t)bm * NV;
        float* o1 = out + (size_t)(rb0 + 8) * (NT * NV) + (size_t)bm * NV;
        #pragma unroll
        for (int f = 0; f < 8; f++) {
            int n = bn * 128 + n0 + f * 8 + tg * 2;
            if (n + 1 < NV) {
                float bv0 = fcb[n], bv1 = fcb[n + 1];
                float2 v0 = on0 ? make_float2(acc[mf][f][0] + bv0, acc[mf][f][1] + bv1)
                                : make_float2(0.f, 0.f);
                float2 v1 = on1 ? make_float2(acc[mf][f][2] + bv0, acc[mf][f][3] + bv1)
                                : make_float2(0.f, 0.f);
                *(float2*)(o0 + n) = v0;
                *(float2*)(o1 + n) = v1;
            }
        }
    }
}

// ---------------- launch ----------------
extern "C" void kernel_launch(void* const* d_in, const int* in_sizes, int n_in,
                              void* d_out, int out_size) {
    const float* images   = (const float*)d_in[0];
    const int*   captions = (const int*)  d_in[1];
    const int*   length   = (const int*)  d_in[2];
    const float* emb      = (const float*)d_in[3];
    const float* Wih      = (const float*)d_in[4];
    const float* Whh      = (const float*)d_in[5];
    const float* bih      = (const float*)d_in[6];
    const float* bhh      = (const float*)d_in[7];
    const float* fcw      = (const float*)d_in[8];
    const float* fcb      = (const float*)d_in[9];
    float* out = (float*)d_out;

    int write_tail = (out_size >= PRED + NB*NS + 2*NB) ? 1 : 0;

    // idempotent + deterministic (no static guards allowed by harness rules)
    cudaFuncSetAttribute(fc_mma_kernel, cudaFuncAttributeMaxDynamicSharedMemorySize, FC_SMEM);

    sort_meta_kernel<<<1, NB>>>(length, captions, out, write_tail);
    cvt_w_kernel<<<(int)(((size_t)NVP*NH + 255) / 256), 256>>>(fcw);
    gather_kernel<<<NS * NB, 128>>>(images, captions, emb);
    gemm_xproj_kernel<<<dim3(NG / 128, (NS * NB) / 128), 256>>>(Wih, bih, bhh);
    for (int s = 0; s < NS; s++)
        cell_kernel<<<dim3(16, 8), 256>>>(s, Whh);
    cvt_h_kernel<<<(int)(((size_t)NT*NB*NH + 255) / 256), 256>>>();
    fc_mma_kernel<<<dim3(NVP / 128, NT), 256, FC_SMEM>>>(fcb, out);
}